// round 4
// baseline (speedup 1.0000x reference)
#include <cuda_runtime.h>
#include <cuda_bf16.h>
#include <cstddef>

// MoEGate: logits = x @ W^T, softmax, top-6 (+renorm), seq-aux loss.
// x: [T=16384, h=2048] f32, W: [E=64, h] f32.
// Output layout (f32): [topk_idx (T*6) | topk_weight (T*6) | aux_loss (1)]
//
// Accuracy-critical: top-k ordering must match jax's fp32 result. We use
// chunked accumulation (64-elem chunks) + Kahan merge so our logits are
// within ~2e-9 of the exact fp32-input dot product, and we rank by logits
// (exactly order-equivalent to softmax scores).

#define NE 64
#define KTOP 6
#define NB 4
#define TPB 32               // tokens per block
#define THREADS 256
#define CHUNK 64
#define XPITCH 68
#define WPITCH 68

__device__ float g_score_sum[NB * NE];
__device__ int   g_cnt[NB * NE];

__global__ void zero_kernel() {
    int i = threadIdx.x;
    if (i < NB * NE) { g_score_sum[i] = 0.0f; g_cnt[i] = 0; }
}

__global__ __launch_bounds__(THREADS) void moe_gate_kernel(
    const float* __restrict__ x, const float* __restrict__ w,
    float* __restrict__ out, int h, int T, int S)
{
    __shared__ __align__(16) float xs[TPB * XPITCH];
    __shared__ __align__(16) float ws[NE * WPITCH];
    __shared__ float logits_s[TPB * NE];
    __shared__ float score_acc[NE];
    __shared__ int   cnt_acc[NE];

    const int tid  = threadIdx.x;
    const int lane = tid & 31;
    const int warp = tid >> 5;
    const int tok0 = blockIdx.x * TPB;

    if (tid < NE) { score_acc[tid] = 0.0f; cnt_acc[tid] = 0; }

    // Kahan running sums + compensations, per (token j, expert half e)
    float sum[4][2], comp[4][2];
#pragma unroll
    for (int j = 0; j < 4; j++)
#pragma unroll
        for (int e = 0; e < 2; e++) { sum[j][e] = 0.0f; comp[j][e] = 0.0f; }

    const float4* x4 = (const float4*)x;
    const float4* w4 = (const float4*)w;
    const int h4 = h >> 2;

    for (int k0 = 0; k0 < h; k0 += CHUNK) {
        const int kq = k0 >> 2;
#pragma unroll
        for (int i = tid; i < TPB * (CHUNK / 4); i += THREADS) {
            int t = i >> 4, q = i & 15;
            float4 v = x4[(size_t)(tok0 + t) * h4 + kq + q];
            *(float4*)(xs + t * XPITCH + q * 4) = v;
        }
#pragma unroll
        for (int i = tid; i < NE * (CHUNK / 4); i += THREADS) {
            int e = i >> 4, q = i & 15;
            float4 v = w4[(size_t)e * h4 + kq + q];
            *(float4*)(ws + e * WPITCH + q * 4) = v;
        }
        __syncthreads();

        // chunk-local accumulators (reset per chunk)
        float c[4][2];
#pragma unroll
        for (int j = 0; j < 4; j++) { c[j][0] = 0.0f; c[j][1] = 0.0f; }

#pragma unroll 4
        for (int kk = 0; kk < CHUNK; kk += 4) {
            float4 w0 = *(const float4*)(ws + lane * WPITCH + kk);
            float4 w1 = *(const float4*)(ws + (lane + 32) * WPITCH + kk);
#pragma unroll
            for (int j = 0; j < 4; j++) {
                float4 xv = *(const float4*)(xs + (warp * 4 + j) * XPITCH + kk);
                c[j][0] += xv.x * w0.x; c[j][0] += xv.y * w0.y;
                c[j][0] += xv.z * w0.z; c[j][0] += xv.w * w0.w;
                c[j][1] += xv.x * w1.x; c[j][1] += xv.y * w1.y;
                c[j][1] += xv.z * w1.z; c[j][1] += xv.w * w1.w;
            }
        }
        // Kahan merge chunk into running sum (no multiplies -> FMA-safe)
#pragma unroll
        for (int j = 0; j < 4; j++)
#pragma unroll
            for (int e = 0; e < 2; e++) {
                float y = c[j][e] - comp[j][e];
                float t = sum[j][e] + y;
                comp[j][e] = (t - sum[j][e]) - y;
                sum[j][e] = t;
            }
        __syncthreads();
    }

#pragma unroll
    for (int j = 0; j < 4; j++) {
        logits_s[(warp * 4 + j) * NE + lane]      = sum[j][0];
        logits_s[(warp * 4 + j) * NE + lane + 32] = sum[j][1];
    }
    __syncthreads();

    // warp-per-token epilogue
    for (int j = 0; j < 4; j++) {
        const int t  = warp * 4 + j;
        const int gt = tok0 + t;
        float v0 = logits_s[t * NE + lane];
        float v1 = logits_s[t * NE + lane + 32];

        float m = fmaxf(v0, v1);
#pragma unroll
        for (int off = 16; off; off >>= 1)
            m = fmaxf(m, __shfl_xor_sync(0xffffffffu, m, off));

        float e0 = __expf(v0 - m), e1 = __expf(v1 - m);
        float z = e0 + e1;
#pragma unroll
        for (int off = 16; off; off >>= 1)
            z += __shfl_xor_sync(0xffffffffu, z, off);
        float inv = 1.0f / z;
        float s0 = e0 * inv, s1 = e1 * inv;

        atomicAdd(&score_acc[lane],      s0);
        atomicAdd(&score_acc[lane + 32], s1);

        // top-6 on LOGITS (order-identical to softmax), stable lowest-index ties
        float a0 = v0, a1 = v1;
        float myw = 0.0f; int myi = 0;
        float wsum = 0.0f;
#pragma unroll
        for (int it = 0; it < KTOP; it++) {
            float bv; int bi;
            if (a0 >= a1) { bv = a0; bi = lane; }
            else          { bv = a1; bi = lane + 32; }
#pragma unroll
            for (int off = 16; off; off >>= 1) {
                float ov = __shfl_xor_sync(0xffffffffu, bv, off);
                int   oi = __shfl_xor_sync(0xffffffffu, bi, off);
                if (ov > bv || (ov == bv && oi < bi)) { bv = ov; bi = oi; }
            }
            // bi is uniform across the warp; fetch its softmax score
            float cand = (bi < 32) ? s0 : s1;
            float sc = __shfl_sync(0xffffffffu, cand, bi & 31);
            wsum += sc;
            if (lane == it) { myw = sc; myi = bi; }
            if (bi == lane)      a0 = -3.4e38f;
            if (bi == lane + 32) a1 = -3.4e38f;
            if (lane == 0) atomicAdd(&cnt_acc[bi], 1);
        }
        if (lane < KTOP) {
            out[(size_t)gt * KTOP + lane] = (float)myi;
            out[(size_t)T * KTOP + (size_t)gt * KTOP + lane] =
                myw / (wsum + 1e-20f);
        }
    }
    __syncthreads();

    if (tid < NE) {
        int b = tok0 / S;
        atomicAdd(&g_score_sum[b * NE + tid], score_acc[tid]);
        atomicAdd(&g_cnt[b * NE + tid],       cnt_acc[tid]);
    }
}

__global__ void aux_kernel(float* __restrict__ out, int T, int S) {
    __shared__ float partial[8];
    const int tid = threadIdx.x;
    const int lane = tid & 31, warp = tid >> 5;
    float v = 0.0f;
    if (tid < NB * NE) {
        float ce = (float)g_cnt[tid] * ((float)NE / ((float)S * (float)KTOP));
        float ms = g_score_sum[tid] / (float)S;
        v = ce * ms;
    }
#pragma unroll
    for (int off = 16; off; off >>= 1)
        v += __shfl_xor_sync(0xffffffffu, v, off);
    if (lane == 0) partial[warp] = v;
    __syncthreads();
    if (tid == 0) {
        float s = 0.0f;
#pragma unroll
        for (int i = 0; i < 8; i++) s += partial[i];
        out[(size_t)2 * T * KTOP] = (s / (float)NB) * 1e-3f;
    }
}

extern "C" void kernel_launch(void* const* d_in, const int* in_sizes, int n_in,
                              void* d_out, int out_size) {
    const float* x = (const float*)d_in[0];
    const float* w = (const float*)d_in[1];
    float* out = (float*)d_out;
    int h = in_sizes[1] / NE;     // 2048
    int T = in_sizes[0] / h;      // 16384
    int S = T / NB;               // 4096

    zero_kernel<<<1, 256>>>();
    moe_gate_kernel<<<T / TPB, THREADS>>>(x, w, out, h, T, S);
    aux_kernel<<<1, 256>>>(out, T, S);
}

// round 5
// speedup vs baseline: 2.0114x; 2.0114x over previous
#include <cuda_runtime.h>
#include <cstddef>
#include <cstdint>

// MoEGate: logits = x @ W^T, softmax, top-6 (+renorm), seq-aux loss.
// x: [T=16384, h=2048] f32, W: [E=64, h] f32.
// Output layout (f32): [topk_idx (T*6) | topk_weight (T*6) | aux_loss (1)]
//
// GEMM engine: fma.rn.f32x2 (Blackwell packed fp32, 2 FMA/instr). The two
// packed halves hold even/odd-k partial sums, so x and w operand pairs are
// naturally contiguous in smem (no duplication/packing). 8 tokens/warp x
// 2 experts/lane register tile balances smem crossbar vs FMA pipe.
// cp.async double-buffered k-chunks, 1 barrier per chunk.
// Accuracy: 32-term chunk partials merged into running packed sums
// (logit error ~1e-8, far below adjacent top-k logit gaps ~1e-3);
// top-6 ranked on logits (exactly order-equivalent to softmax).

#define NE 64
#define KTOP 6
#define NB 4
#define TPB 32               // tokens per block
#define THREADS 128          // 4 warps, 8 tokens/warp
#define CHUNK 32             // k elements per stage
#define PITCH 36             // floats per staged row (144B; quad-stride 9 -> conflict-free)

__device__ float g_score_sum[NB * NE];
__device__ int   g_cnt[NB * NE];

__global__ void zero_kernel() {
    int i = threadIdx.x;
    if (i < NB * NE) { g_score_sum[i] = 0.0f; g_cnt[i] = 0; }
}

static __device__ __forceinline__ void ffma2(unsigned long long& d,
                                             unsigned long long a,
                                             unsigned long long b) {
    asm("fma.rn.f32x2 %0, %1, %2, %0;" : "+l"(d) : "l"(a), "l"(b));
}
static __device__ __forceinline__ void add2(unsigned long long& d,
                                            unsigned long long a) {
    asm("add.rn.f32x2 %0, %0, %1;" : "+l"(d) : "l"(a));
}
static __device__ __forceinline__ void cpa16(uint32_t dst, const void* src) {
    asm volatile("cp.async.cg.shared.global [%0], [%1], 16;"
                 :: "r"(dst), "l"(src));
}

__global__ __launch_bounds__(THREADS) void moe_gate_kernel(
    const float* __restrict__ x, const float* __restrict__ w,
    float* __restrict__ out, int h, int T, int S)
{
    __shared__ __align__(16) float xs[2][TPB * PITCH];
    __shared__ __align__(16) float ws[2][NE * PITCH];
    __shared__ float score_acc[NE];
    __shared__ int   cnt_acc[NE];

    const int tid  = threadIdx.x;
    const int lane = tid & 31;
    const int warp = tid >> 5;
    const int tok0 = blockIdx.x * TPB;
    const int nchunk = h / CHUNK;

    if (tid < NE) { score_acc[tid] = 0.0f; cnt_acc[tid] = 0; }

    // packed accumulators: halves = even-k / odd-k partial sums
    unsigned long long acc[8][2], sum[8][2];
#pragma unroll
    for (int t = 0; t < 8; t++) {
        acc[t][0] = 0ull; acc[t][1] = 0ull;
        sum[t][0] = 0ull; sum[t][1] = 0ull;
    }

    // ---- staging: 96 rows (32 x + 64 w) x 8 16B-quads = 768 jobs / 128 thr
    auto stage = [&](int k0, int buf) {
#pragma unroll
        for (int j = 0; j < 6; j++) {
            int c = tid + j * THREADS;
            int row = c >> 3, q = c & 7;
            const float* src;
            float* dst;
            if (row < TPB) {
                src = x + (size_t)(tok0 + row) * h + k0 + q * 4;
                dst = &xs[buf][row * PITCH + q * 4];
            } else {
                int e = row - TPB;
                src = w + (size_t)e * h + k0 + q * 4;
                dst = &ws[buf][e * PITCH + q * 4];
            }
            cpa16((uint32_t)__cvta_generic_to_shared(dst), src);
        }
    };

    stage(0, 0);
    asm volatile("cp.async.commit_group;" ::: "memory");

    for (int c = 0; c < nchunk; c++) {
        const int buf = c & 1;
        asm volatile("cp.async.wait_group 0;" ::: "memory");
        __syncthreads();   // chunk c visible to all; all done reading buf^1

        if (c + 1 < nchunk) {
            stage((c + 1) * CHUNK, buf ^ 1);
            asm volatile("cp.async.commit_group;" ::: "memory");
        }

        const float* xb = &xs[buf][(warp * 8) * PITCH];
        const float* wb = &ws[buf][0];
#pragma unroll
        for (int kk = 0; kk < CHUNK; kk += 4) {
            ulonglong2 w0 = *(const ulonglong2*)(wb + lane * PITCH + kk);
            ulonglong2 w1 = *(const ulonglong2*)(wb + (lane + 32) * PITCH + kk);
#pragma unroll
            for (int t = 0; t < 8; t++) {
                ulonglong2 xv = *(const ulonglong2*)(xb + t * PITCH + kk);
                ffma2(acc[t][0], xv.x, w0.x);
                ffma2(acc[t][0], xv.y, w0.y);
                ffma2(acc[t][1], xv.x, w1.x);
                ffma2(acc[t][1], xv.y, w1.y);
            }
        }
        // merge 32-term chunk partials into running sums, reset
#pragma unroll
        for (int t = 0; t < 8; t++) {
            add2(sum[t][0], acc[t][0]); acc[t][0] = 0ull;
            add2(sum[t][1], acc[t][1]); acc[t][1] = 0ull;
        }
    }

    // ---- epilogue: warp owns tokens warp*8 .. warp*8+7; lane owns experts
    // lane and lane+32. Logits never leave registers.
    union Cv { unsigned long long u; float2 f; };
    for (int j = 0; j < 8; j++) {
        const int t  = warp * 8 + j;
        const int gt = tok0 + t;
        Cv c0, c1; c0.u = sum[j][0]; c1.u = sum[j][1];
        float v0 = c0.f.x + c0.f.y;
        float v1 = c1.f.x + c1.f.y;

        float m = fmaxf(v0, v1);
#pragma unroll
        for (int off = 16; off; off >>= 1)
            m = fmaxf(m, __shfl_xor_sync(0xffffffffu, m, off));

        float e0 = __expf(v0 - m), e1 = __expf(v1 - m);
        float z = e0 + e1;
#pragma unroll
        for (int off = 16; off; off >>= 1)
            z += __shfl_xor_sync(0xffffffffu, z, off);
        float inv = 1.0f / z;
        float s0 = e0 * inv, s1 = e1 * inv;

        atomicAdd(&score_acc[lane],      s0);
        atomicAdd(&score_acc[lane + 32], s1);

        // top-6 on LOGITS, stable lowest-index tie-break
        float a0 = v0, a1 = v1;
        float myw = 0.0f; int myi = 0;
        float wsum = 0.0f;
#pragma unroll
        for (int it = 0; it < KTOP; it++) {
            float bv; int bi;
            if (a0 >= a1) { bv = a0; bi = lane; }
            else          { bv = a1; bi = lane + 32; }
#pragma unroll
            for (int off = 16; off; off >>= 1) {
                float ov = __shfl_xor_sync(0xffffffffu, bv, off);
                int   oi = __shfl_xor_sync(0xffffffffu, bi, off);
                if (ov > bv || (ov == bv && oi < bi)) { bv = ov; bi = oi; }
            }
            float cand = (bi < 32) ? s0 : s1;
            float sc = __shfl_sync(0xffffffffu, cand, bi & 31);
            wsum += sc;
            if (lane == it) { myw = sc; myi = bi; }
            if (bi == lane)      a0 = -3.4e38f;
            if (bi == lane + 32) a1 = -3.4e38f;
            if (lane == 0) atomicAdd(&cnt_acc[bi], 1);
        }
        if (lane < KTOP) {
            out[(size_t)gt * KTOP + lane] = (float)myi;
            out[(size_t)T * KTOP + (size_t)gt * KTOP + lane] =
                myw / (wsum + 1e-20f);
        }
    }
    __syncthreads();

    if (tid < NE) {
        int b = tok0 / S;
        atomicAdd(&g_score_sum[b * NE + tid], score_acc[tid]);
        atomicAdd(&g_cnt[b * NE + tid],       cnt_acc[tid]);
    }
}

__global__ void aux_kernel(float* __restrict__ out, int T, int S) {
    __shared__ float partial[8];
    const int tid = threadIdx.x;
    const int lane = tid & 31, warp = tid >> 5;
    float v = 0.0f;
    if (tid < NB * NE) {
        float ce = (float)g_cnt[tid] * ((float)NE / ((float)S * (float)KTOP));
        float ms = g_score_sum[tid] / (float)S;
        v = ce * ms;
    }
#pragma unroll
    for (int off = 16; off; off >>= 1)
        v += __shfl_xor_sync(0xffffffffu, v, off);
    if (lane == 0) partial[warp] = v;
    __syncthreads();
    if (tid == 0) {
        float s = 0.0f;
#pragma unroll
        for (int i = 0; i < 8; i++) s += partial[i];
        out[(size_t)2 * T * KTOP] = (s / (float)NB) * 1e-3f;
    }
}

extern "C" void kernel_launch(void* const* d_in, const int* in_sizes, int n_in,
                              void* d_out, int out_size) {
    const float* x = (const float*)d_in[0];
    const float* w = (const float*)d_in[1];
    float* out = (float*)d_out;
    int h = in_sizes[1] / NE;     // 2048
    int T = in_sizes[0] / h;      // 16384
    int S = T / NB;               // 4096

    zero_kernel<<<1, 256>>>();
    moe_gate_kernel<<<T / TPB, THREADS>>>(x, w, out, h, T, S);
    aux_kernel<<<1, 256>>>(out, T, S);
}